// round 16
// baseline (speedup 1.0000x reference)
#include <cuda_runtime.h>
#include <cuda_bf16.h>
#include <math.h>
#include <stdint.h>

#define BATCH 64
#define SEQT  512
#define EDIM  300
#define KB16  320      // bf16 K padding (one segment)
#define K3    960      // 3 segments: A=[hi,lo,hi], B=[hi,hi,lo]
#define HC    512
#define G4    2048     // 4*HC
#define NBLK  128
#define NGRP  32       // blocks per bq barrier group

typedef unsigned long long ull;

// ---- scratch (device globals: allocation-free rule) ----
// XG/XB rows are BATCH-MAJOR: r = b*512 + t  (enables dead-tile skip)
__device__ float g_XG[(size_t)SEQT * BATCH * G4];          // [r][g]
__device__ unsigned short g_XB[(size_t)SEQT * BATCH * K3]; // bf16 A'' [r][960]
__device__ unsigned short g_WB[(size_t)G4 * K3];           // bf16 B'' [n][960]
__device__ float g_H[2][BATCH * HC];
__device__ unsigned int g_count4[4];                       // per-bq arrive counters
__device__ unsigned int g_epoch4[4];                       // per-bq epochs

#define OUT_CELL_OFF  ((size_t)BATCH * SEQT * HC)
#define OUT_H_OFF     (2 * OUT_CELL_OFF)
#define OUT_C_OFF     (OUT_H_OFF + (size_t)BATCH * HC)

// ---------------- packed fp32x2 helpers ----------------
__device__ __forceinline__ ull ffma2(ull a, ull b, ull c) {
    ull d;
    asm("fma.rn.f32x2 %0, %1, %2, %3;" : "=l"(d) : "l"(a), "l"(b), "l"(c));
    return d;
}
__device__ __forceinline__ float hsum2(ull v) {
    unsigned a, b;
    asm("mov.b64 {%0, %1}, %2;" : "=r"(a), "=r"(b) : "l"(v));
    return __uint_as_float(a) + __uint_as_float(b);
}

// ---------------- fast, overflow-robust activations ----------------
__device__ __forceinline__ float fsigmoid(float x) {
    return __fdividef(1.f, 1.f + __expf(-x));
}
__device__ __forceinline__ float ftanh(float x) {
    float ax = fabsf(x);
    float e  = __expf(2.f * ax);
    float r  = 1.f - __fdividef(2.f, e + 1.f);
    return copysignf(r, x);
}

// ---------------- L2-scope (.cg) accessors ----------------
__device__ __forceinline__ float ldcg_f(const float* p) {
    float v;
    asm volatile("ld.global.cg.f32 %0, [%1];" : "=f"(v) : "l"(p));
    return v;
}
__device__ __forceinline__ void stcg_f(float* p, float v) {
    asm volatile("st.global.cg.f32 [%0], %1;" :: "l"(p), "f"(v));
}

// ---------------- cp.async ----------------
__device__ __forceinline__ void cp16(unsigned smem_dst, const void* gsrc) {
    asm volatile("cp.async.cg.shared.global [%0], [%1], 16;"
                 :: "r"(smem_dst), "l"(gsrc));
}
#define CP_COMMIT()  asm volatile("cp.async.commit_group;" ::: "memory")
#define CP_WAIT(N)   asm volatile("cp.async.wait_group %0;" :: "n"(N) : "memory")

// ---------------- scoped-atomic barrier primitives (R10) ----------------
__device__ __forceinline__ unsigned ld_acq(const unsigned* p) {
    unsigned v;
    asm volatile("ld.acquire.gpu.global.u32 %0, [%1];" : "=r"(v) : "l"(p) : "memory");
    return v;
}
__device__ __forceinline__ void st_rel(unsigned* p, unsigned v) {
    asm volatile("st.release.gpu.global.u32 [%0], %1;" :: "l"(p), "r"(v) : "memory");
}
__device__ __forceinline__ unsigned atom_add_rel(unsigned* p, unsigned v) {
    unsigned old;
    asm volatile("atom.release.gpu.global.add.u32 %0, [%1], %2;"
                 : "=r"(old) : "l"(p), "r"(v) : "memory");
    return old;
}
__device__ __forceinline__ void bar_arrive(int bq, unsigned target) {
    if (atom_add_rel(&g_count4[bq], 1) == NGRP - 1) {
        g_count4[bq] = 0;
        st_rel(&g_epoch4[bq], target);
    }
}
__device__ __forceinline__ void bar_wait(int bq, unsigned target) {
    while (ld_acq(&g_epoch4[bq]) != target) { }
}

// ---------------------------------------------------------------------------
// Zero-prefill output + cell regions.
// ---------------------------------------------------------------------------
__global__ void zero_out(float* __restrict__ out) {
    size_t i = ((size_t)blockIdx.x * 256 + threadIdx.x) * 4;
    *(float4*)(out + i) = make_float4(0.f, 0.f, 0.f, 0.f);
}

// ---------------------------------------------------------------------------
// Build B'' = [hi(W), hi(W), lo(W)] bf16, K padded 300->320 with zeros.
// ---------------------------------------------------------------------------
__global__ void prep_WB(const float* __restrict__ W_ih) {
    int idx = blockIdx.x * 256 + threadIdx.x;   // 2048*320
    int n = idx / KB16;
    int k = idx - n * KB16;
    float w = (k < EDIM) ? W_ih[(size_t)n * EDIM + k] : 0.f;
    __nv_bfloat16 hi = __float2bfloat16(w);
    __nv_bfloat16 lo = __float2bfloat16(w - __bfloat162float(hi));
    unsigned short* p = g_WB + (size_t)n * K3;
    p[k]            = __bfloat16_as_ushort(hi);
    p[KB16 + k]     = __bfloat16_as_ushort(hi);
    p[2 * KB16 + k] = __bfloat16_as_ushort(lo);
}

// ---------------------------------------------------------------------------
// Build A'' = [hi(x), lo(x), hi(x)] bf16 per GEMM row r = b*512 + t.
// Dead-row skip: rows with t >= len_b feed only XG entries that lstm never
// reads (every read is t < len_b guarded), so skip the work.
// ---------------------------------------------------------------------------
__global__ void prep_X(const int* __restrict__ seq,
                       const float* __restrict__ emb,
                       const int* __restrict__ lengths) {
    size_t idx = (size_t)blockIdx.x * 256 + threadIdx.x;  // 32768*320
    int r = (int)(idx / KB16);
    int k = (int)(idx - (size_t)r * KB16);
    int b = r >> 9;           // batch-major rows
    int t = r & 511;
    if (t >= lengths[b]) return;
    int tok = seq[b * SEQT + t];
    float x = (k < EDIM) ? emb[(size_t)tok * EDIM + k] : 0.f;
    __nv_bfloat16 hi = __float2bfloat16(x);
    __nv_bfloat16 lo = __float2bfloat16(x - __bfloat162float(hi));
    unsigned short* p = g_XB + (size_t)r * K3;
    p[k]            = __bfloat16_as_ushort(hi);
    p[KB16 + k]     = __bfloat16_as_ushort(lo);
    p[2 * KB16 + k] = __bfloat16_as_ushort(hi);
}

// ---------------- warp-level bf16 MMA ----------------
__device__ __forceinline__ void mma16816(float* d,
                                         const unsigned* a,
                                         const unsigned* b) {
    asm volatile(
        "mma.sync.aligned.m16n8k16.row.col.f32.bf16.bf16.f32 "
        "{%0,%1,%2,%3}, {%4,%5,%6,%7}, {%8,%9}, {%0,%1,%2,%3};"
        : "+f"(d[0]), "+f"(d[1]), "+f"(d[2]), "+f"(d[3])
        : "r"(a[0]), "r"(a[1]), "r"(a[2]), "r"(a[3]),
          "r"(b[0]), "r"(b[1]));
}

// ---------------------------------------------------------------------------
// Tensor-core input GEMM (R15: 128x128x32, warp 64x32, dead-tile skip).
// ---------------------------------------------------------------------------
#define KPITCH 40
#define NCHUNK 30

__global__ void __launch_bounds__(256) tc_embed_gemm(
    const float* __restrict__ b_ih,
    const float* __restrict__ b_hh,
    const int*   __restrict__ lengths)
{
    __shared__ __align__(16) unsigned short As[2][128 * KPITCH];
    __shared__ __align__(16) unsigned short Bs[2][128 * KPITCH];
    __shared__ float sbias[128];

    const int mt = blockIdx.y;
    const int nt = blockIdx.x;

    // dead-tile skip (uniform across block)
    if (lengths[mt >> 2] <= (mt & 3) * 128) return;

    const int tid = threadIdx.x;
    const int wid = tid >> 5;
    const int lane = tid & 31;
    const int g   = lane >> 2;
    const int t2  = lane & 3;
    const int wm  = wid >> 2;
    const int wn  = wid & 3;

    if (tid < 128) {
        int n = nt * 128 + tid;
        sbias[tid] = b_ih[n] + b_hh[n];
    }

    const unsigned short* Abase = g_XB + (size_t)(mt * 128) * K3;
    const unsigned short* Bbase = g_WB + (size_t)(nt * 128) * K3;

    unsigned a_sm = 0, b_sm = 0;
    asm("{ .reg .u64 t; cvta.to.shared.u64 t, %1; cvt.u32.u64 %0, t; }"
        : "=r"(a_sm) : "l"((const void*)As));
    asm("{ .reg .u64 t; cvta.to.shared.u64 t, %1; cvt.u32.u64 %0, t; }"
        : "=r"(b_sm) : "l"((const void*)Bs));

#define LOAD_CHUNK(buf, c) do {                                               \
    _Pragma("unroll")                                                         \
    for (int i = 0; i < 2; i++) {                                             \
        int lin = tid + i * 256;                                              \
        int row = lin >> 2;                                                   \
        int q   = lin & 3;                                                    \
        cp16(a_sm + (buf) * (128 * KPITCH * 2) + row * (KPITCH * 2) + q * 16, \
             Abase + (size_t)row * K3 + (c) * 32 + q * 8);                    \
    }                                                                         \
    _Pragma("unroll")                                                         \
    for (int i = 0; i < 2; i++) {                                             \
        int lin = tid + i * 256;                                              \
        int row = lin >> 2;                                                   \
        int q   = lin & 3;                                                    \
        cp16(b_sm + (buf) * (128 * KPITCH * 2) + row * (KPITCH * 2) + q * 16, \
             Bbase + (size_t)row * K3 + (c) * 32 + q * 8);                    \
    }                                                                         \
    CP_COMMIT();                                                              \
} while (0)

    float acc[4][4][4];
#pragma unroll
    for (int mf = 0; mf < 4; mf++)
#pragma unroll
        for (int nf = 0; nf < 4; nf++)
#pragma unroll
            for (int q = 0; q < 4; q++) acc[mf][nf][q] = 0.f;

    LOAD_CHUNK(0, 0);

#pragma unroll 1
    for (int c = 0; c < NCHUNK; c++) {
        const int buf = c & 1;
        if (c + 1 < NCHUNK) {
            LOAD_CHUNK(buf ^ 1, c + 1);
            CP_WAIT(1);
        } else {
            CP_WAIT(0);
        }
        __syncthreads();

        const unsigned short* Ab = As[buf];
        const unsigned short* Bb = Bs[buf];

#pragma unroll
        for (int k16 = 0; k16 < 2; k16++) {
            const int ko = k16 * 16 + t2 * 2;
            unsigned af[4][4];
#pragma unroll
            for (int mf = 0; mf < 4; mf++) {
                int row = wm * 64 + mf * 16 + g;
                af[mf][0] = *(const unsigned*)&Ab[row * KPITCH + ko];
                af[mf][1] = *(const unsigned*)&Ab[(row + 8) * KPITCH + ko];
                af[mf][2] = *(const unsigned*)&Ab[row * KPITCH + ko + 8];
                af[mf][3] = *(const unsigned*)&Ab[(row + 8) * KPITCH + ko + 8];
            }
            unsigned bfr[4][2];
#pragma unroll
            for (int nf = 0; nf < 4; nf++) {
                int col = wn * 32 + nf * 8 + g;
                bfr[nf][0] = *(const unsigned*)&Bb[col * KPITCH + ko];
                bfr[nf][1] = *(const unsigned*)&Bb[col * KPITCH + ko + 8];
            }
#pragma unroll
            for (int mf = 0; mf < 4; mf++)
#pragma unroll
                for (int nf = 0; nf < 4; nf++)
                    mma16816(acc[mf][nf], af[mf], bfr[nf]);
        }
        __syncthreads();
    }
#undef LOAD_CHUNK

    const int r0 = mt * 128 + wm * 64;
#pragma unroll
    for (int mf = 0; mf < 4; mf++) {
#pragma unroll
        for (int nf = 0; nf < 4; nf++) {
            int nl = wn * 32 + nf * 8 + t2 * 2;
            int n  = nt * 128 + nl;
            float bx = sbias[nl];
            float by = sbias[nl + 1];
            int ra = r0 + mf * 16 + g;
            int rb = ra + 8;
            *(float2*)(g_XG + (size_t)ra * G4 + n) =
                make_float2(acc[mf][nf][0] + bx, acc[mf][nf][1] + by);
            *(float2*)(g_XG + (size_t)rb * G4 + n) =
                make_float2(acc[mf][nf][2] + bx, acc[mf][nf][3] + by);
        }
    }
}

// ---------------------------------------------------------------------------
// Persistent LSTM — R15 structure (best measured); GEMV now uses 4
// accumulators per row-pair to break the FFMA2 RAW chains.
// ---------------------------------------------------------------------------
__global__ void __launch_bounds__(256, 1) lstm_persistent(
    const float* __restrict__ W_hh,
    const int*   __restrict__ lengths,
    float* __restrict__ out)
{
    __shared__ float sm_h[16 * HC];
    __shared__ float Ex[64 * 17];
    __shared__ int   sl[16];

    const int tid  = threadIdx.x;
    const int bk   = blockIdx.x;
    const int jg   = bk >> 2;
    const int bq   = bk & 3;
    const int lane = tid & 31;
    const int w    = tid >> 5;
    const int rp   = lane >> 3;
    const int kc   = lane & 7;

    const int lr0 = w * 8 + rp * 2;
    const int lr1 = lr0 + 1;
    const int row0 = ((lr0 >> 4) << 9) + jg * 16 + (lr0 & 15);
    const int row1 = ((lr1 >> 4) << 9) + jg * 16 + (lr1 & 15);

    ull W0[32], W1[32];
#pragma unroll
    for (int m = 0; m < 16; m++) {
        const float* p0 = W_hh + (size_t)row0 * HC + m * 32 + kc * 4;
        const float* p1 = W_hh + (size_t)row1 * HC + m * 32 + kc * 4;
        ulonglong2 v0 = *(const ulonglong2*)p0;
        ulonglong2 v1 = *(const ulonglong2*)p1;
        W0[2 * m] = v0.x; W0[2 * m + 1] = v0.y;
        W1[2 * m] = v1.x; W1[2 * m + 1] = v1.y;
    }

    const unsigned sm_h_u32 = (unsigned)__cvta_generic_to_shared(sm_h);

    // replay-safe epoch base (read by all threads before any arrive)
    const unsigned e0 = ld_acq(&g_epoch4[bq]);

    if (tid < 16) sl[tid] = lengths[bq * 16 + tid];

    const int jl   = tid & 15;
    const int bl   = tid >> 4;
    const int b_pt = bq * 16 + bl;
    const int j_pt = jg * 16 + jl;
    float h_st = 0.f, c_st = 0.f;

    stcg_f(&g_H[0][(b_pt << 9) + j_pt], 0.f);

    __syncthreads();
    int gmax = sl[0];
#pragma unroll
    for (int i = 1; i < 16; i++) gmax = max(gmax, sl[i]);
    const int len_b = sl[bl];

    if (tid == 0) bar_arrive(bq, e0 + 1);
    bar_wait(bq, e0 + 1);

    // batch-major xg rows: base row = b_pt*512
    const float* xg_base = g_XG + ((size_t)b_pt << 9) * G4;

    float xi, xf, xgv, xo;
    {
        const float* xg = xg_base;      // t = 0
        xi  = ldcg_f(xg + j_pt);
        xf  = ldcg_f(xg + 512 + j_pt);
        xgv = ldcg_f(xg + 1024 + j_pt);
        xo  = ldcg_f(xg + 1536 + j_pt);
    }

#define GEMV_BATCH(bb)                                                        \
    if (t < sl[bb]) {                                                         \
        const float* hb = sm_h + ((bb) << 9) + (kc << 2);                     \
        ull a0x = 0ull, a0y = 0ull, a1x = 0ull, a1y = 0ull;                   \
        _Pragma("unroll")                                                     \
        for (int m = 0; m < 16; m++) {                                        \
            ulonglong2 hv = *(const ulonglong2*)(hb + (m << 5));              \
            a0x = ffma2(W0[2 * m],     hv.x, a0x);                            \
            a0y = ffma2(W0[2 * m + 1], hv.y, a0y);                            \
            a1x = ffma2(W1[2 * m],     hv.x, a1x);                            \
            a1y = ffma2(W1[2 * m + 1], hv.y, a1y);                            \
        }                                                                     \
        float s0 = hsum2(a0x) + hsum2(a0y);                                   \
        float s1 = hsum2(a1x) + hsum2(a1y);                                   \
        s0 += __shfl_xor_sync(0xffffffffu, s0, 1);                            \
        s0 += __shfl_xor_sync(0xffffffffu, s0, 2);                            \
        s0 += __shfl_xor_sync(0xffffffffu, s0, 4);                            \
        s1 += __shfl_xor_sync(0xffffffffu, s1, 1);                            \
        s1 += __shfl_xor_sync(0xffffffffu, s1, 2);                            \
        s1 += __shfl_xor_sync(0xffffffffu, s1, 4);                            \
        if (kc == 0) {                                                        \
            Ex[lr0 * 17 + (bb)] = s0;                                         \
            Ex[lr1 * 17 + (bb)] = s1;                                         \
        }                                                                     \
    }

#pragma unroll 1
    for (int t = 0; t < gmax; t++) {
        const int p = t & 1;
        const float* h_in = g_H[p] + ((bq * 16) << 9);

        // ---- stage this bq's h (16 rows x 512) in two 8-batch halves ----
#pragma unroll
        for (int grp = 0; grp < 2; grp++) {
#pragma unroll
            for (int i = 0; i < 4; i++) {
                int lin = tid + (i << 8);
                int r   = lin >> 7;
                int off = (lin & 127) << 2;
                int b   = grp * 8 + r;
                cp16(sm_h_u32 + (unsigned)((((b << 9) + off) << 2)),
                     h_in + (b << 9) + off);
            }
            CP_COMMIT();
        }
        CP_WAIT(1);
        __syncthreads();

#pragma unroll 2
        for (int bb = 0; bb < 8; bb++) GEMV_BATCH(bb)

        CP_WAIT(0);
        __syncthreads();

#pragma unroll 2
        for (int bb = 8; bb < 16; bb++) GEMV_BATCH(bb)

        __syncthreads();

        const bool msk = (t < len_b);
        if (msk) {
            float pi = xi  + Ex[(0  + jl) * 17 + bl];
            float pf = xf  + Ex[(16 + jl) * 17 + bl];
            float pg = xgv + Ex[(32 + jl) * 17 + bl];
            float po = xo  + Ex[(48 + jl) * 17 + bl];

            float gi = fsigmoid(pi);
            float gf = fsigmoid(pf);
            float gg = ftanh(pg);
            float go = fsigmoid(po);

            c_st = gf * c_st + gi * gg;
            h_st = go * ftanh(c_st);
        }
        stcg_f(&g_H[p ^ 1][(b_pt << 9) + j_pt], h_st);

        const bool last = (t + 1 >= gmax);
        __syncthreads();                 // all publishes issued
        if (!last && tid == 0) bar_arrive(bq, e0 + t + 2);

        // DRAM out-stores + next-step xg prefetch hide in the barrier shadow
        if (msk) {
            size_t o = (size_t)b_pt * (SEQT * HC) + (size_t)t * HC + j_pt;
            out[o]                = h_st;
            out[OUT_CELL_OFF + o] = c_st;
        }
        if (t + 1 < len_b) {
            const float* xg = xg_base + (size_t)(t + 1) * G4;
            xi  = ldcg_f(xg + j_pt);
            xf  = ldcg_f(xg + 512 + j_pt);
            xgv = ldcg_f(xg + 1024 + j_pt);
            xo  = ldcg_f(xg + 1536 + j_pt);
        }

        if (!last) bar_wait(bq, e0 + t + 2);
    }

    {
        size_t e = (size_t)b_pt * HC + j_pt;
        out[OUT_H_OFF + e] = h_st;
        out[OUT_C_OFF + e] = c_st;
    }
#undef GEMV_BATCH
}

// ---------------------------------------------------------------------------
extern "C" void kernel_launch(void* const* d_in, const int* in_sizes, int n_in,
                              void* d_out, int out_size) {
    const int*   seq     = (const int*)d_in[0];
    const int*   lengths = (const int*)d_in[1];
    const float* emb     = (const float*)d_in[2];
    const float* W_ih    = (const float*)d_in[3];
    const float* W_hh    = (const float*)d_in[4];
    const float* b_ih    = (const float*)d_in[5];
    const float* b_hh    = (const float*)d_in[6];
    float* out = (float*)d_out;

    zero_out<<<(unsigned)(2 * OUT_CELL_OFF / (256 * 4)), 256>>>(out);
    prep_WB<<<(G4 * KB16) / 256, 256>>>(W_ih);
    prep_X<<<(unsigned)(((size_t)SEQT * BATCH * KB16) / 256), 256>>>(seq, emb, lengths);
    tc_embed_gemm<<<dim3(G4 / 128, (SEQT * BATCH) / 128), 256>>>(b_ih, b_hh, lengths);
    lstm_persistent<<<NBLK, 256>>>(W_hh, lengths, out);
}

// round 17
// speedup vs baseline: 1.0364x; 1.0364x over previous
#include <cuda_runtime.h>
#include <cuda_bf16.h>
#include <math.h>
#include <stdint.h>

#define BATCH 64
#define SEQT  512
#define EDIM  300
#define KB16  320      // bf16 K padding (one segment)
#define K3    960      // 3 segments: A=[hi,lo,hi], B=[hi,hi,lo]
#define HC    512
#define G4    2048     // 4*HC
#define NBLK  128
#define NGRP  32       // blocks per bq barrier group

typedef unsigned long long ull;

// ---- scratch (device globals: allocation-free rule) ----
// XG/XB rows are BATCH-MAJOR: r = b*512 + t  (enables dead-tile skip)
__device__ float g_XG[(size_t)SEQT * BATCH * G4];          // [r][g]
__device__ unsigned short g_XB[(size_t)SEQT * BATCH * K3]; // bf16 A'' [r][960]
__device__ unsigned short g_WB[(size_t)G4 * K3];           // bf16 B'' [n][960]
__device__ float g_H[2][BATCH * HC];
__device__ unsigned int g_count4[4];                       // per-bq arrive counters
__device__ unsigned int g_epoch4[4];                       // per-bq epochs

#define OUT_CELL_OFF  ((size_t)BATCH * SEQT * HC)
#define OUT_H_OFF     (2 * OUT_CELL_OFF)
#define OUT_C_OFF     (OUT_H_OFF + (size_t)BATCH * HC)

// ---------------- packed fp32x2 helpers ----------------
__device__ __forceinline__ ull ffma2(ull a, ull b, ull c) {
    ull d;
    asm("fma.rn.f32x2 %0, %1, %2, %3;" : "=l"(d) : "l"(a), "l"(b), "l"(c));
    return d;
}
__device__ __forceinline__ float hsum2(ull v) {
    unsigned a, b;
    asm("mov.b64 {%0, %1}, %2;" : "=r"(a), "=r"(b) : "l"(v));
    return __uint_as_float(a) + __uint_as_float(b);
}

// ---------------- fast, overflow-robust activations ----------------
__device__ __forceinline__ float fsigmoid(float x) {
    return __fdividef(1.f, 1.f + __expf(-x));
}
__device__ __forceinline__ float ftanh(float x) {
    float ax = fabsf(x);
    float e  = __expf(2.f * ax);
    float r  = 1.f - __fdividef(2.f, e + 1.f);
    return copysignf(r, x);
}

// ---------------- L2-scope (.cg) accessors ----------------
__device__ __forceinline__ float ldcg_f(const float* p) {
    float v;
    asm volatile("ld.global.cg.f32 %0, [%1];" : "=f"(v) : "l"(p));
    return v;
}
__device__ __forceinline__ void stcg_f(float* p, float v) {
    asm volatile("st.global.cg.f32 [%0], %1;" :: "l"(p), "f"(v));
}

// ---------------- cp.async ----------------
__device__ __forceinline__ void cp16(unsigned smem_dst, const void* gsrc) {
    asm volatile("cp.async.cg.shared.global [%0], [%1], 16;"
                 :: "r"(smem_dst), "l"(gsrc));
}
#define CP_COMMIT()  asm volatile("cp.async.commit_group;" ::: "memory")
#define CP_WAIT(N)   asm volatile("cp.async.wait_group %0;" :: "n"(N) : "memory")

// ---------------- scoped-atomic barrier primitives (R10) ----------------
__device__ __forceinline__ unsigned ld_acq(const unsigned* p) {
    unsigned v;
    asm volatile("ld.acquire.gpu.global.u32 %0, [%1];" : "=r"(v) : "l"(p) : "memory");
    return v;
}
__device__ __forceinline__ void st_rel(unsigned* p, unsigned v) {
    asm volatile("st.release.gpu.global.u32 [%0], %1;" :: "l"(p), "r"(v) : "memory");
}
__device__ __forceinline__ unsigned atom_add_rel(unsigned* p, unsigned v) {
    unsigned old;
    asm volatile("atom.release.gpu.global.add.u32 %0, [%1], %2;"
                 : "=r"(old) : "l"(p), "r"(v) : "memory");
    return old;
}
__device__ __forceinline__ void bar_arrive(int bq, unsigned target) {
    if (atom_add_rel(&g_count4[bq], 1) == NGRP - 1) {
        g_count4[bq] = 0;
        st_rel(&g_epoch4[bq], target);
    }
}
__device__ __forceinline__ void bar_wait(int bq, unsigned target) {
    while (ld_acq(&g_epoch4[bq]) != target) { }
}

// ---------------------------------------------------------------------------
// Zero-prefill output + cell regions — DEAD CELLS ONLY (t >= len_b); live
// cells (t < len_b) are always written by lstm's masked stores.
// Grid covers one region (B*T*HC/4 float4 per region); z dim picks region.
// ---------------------------------------------------------------------------
__global__ void zero_out(float* __restrict__ out,
                         const int* __restrict__ lengths) {
    size_t i = ((size_t)blockIdx.x * 256 + threadIdx.x) * 4;   // float idx
    int b = (int)(i >> 18);            // / (512*512)
    int t = (int)((i >> 9) & 511);     // / 512 % 512
    if (t < lengths[b]) return;        // live cell: lstm will write it
    float* base = out + (size_t)blockIdx.y * OUT_CELL_OFF;
    *(float4*)(base + i) = make_float4(0.f, 0.f, 0.f, 0.f);
}

// ---------------------------------------------------------------------------
// Build B'' = [hi(W), hi(W), lo(W)] bf16, K padded 300->320 with zeros.
// ---------------------------------------------------------------------------
__global__ void prep_WB(const float* __restrict__ W_ih) {
    int idx = blockIdx.x * 256 + threadIdx.x;   // 2048*320
    int n = idx / KB16;
    int k = idx - n * KB16;
    float w = (k < EDIM) ? W_ih[(size_t)n * EDIM + k] : 0.f;
    __nv_bfloat16 hi = __float2bfloat16(w);
    __nv_bfloat16 lo = __float2bfloat16(w - __bfloat162float(hi));
    unsigned short* p = g_WB + (size_t)n * K3;
    p[k]            = __bfloat16_as_ushort(hi);
    p[KB16 + k]     = __bfloat16_as_ushort(hi);
    p[2 * KB16 + k] = __bfloat16_as_ushort(lo);
}

// ---------------------------------------------------------------------------
// Build A'' = [hi(x), lo(x), hi(x)] bf16 per GEMM row r = b*512 + t.
// Dead-row skip: rows with t >= len_b feed only XG entries never read.
// ---------------------------------------------------------------------------
__global__ void prep_X(const int* __restrict__ seq,
                       const float* __restrict__ emb,
                       const int* __restrict__ lengths) {
    size_t idx = (size_t)blockIdx.x * 256 + threadIdx.x;  // 32768*320
    int r = (int)(idx / KB16);
    int k = (int)(idx - (size_t)r * KB16);
    int b = r >> 9;           // batch-major rows
    int t = r & 511;
    if (t >= lengths[b]) return;
    int tok = seq[b * SEQT + t];
    float x = (k < EDIM) ? emb[(size_t)tok * EDIM + k] : 0.f;
    __nv_bfloat16 hi = __float2bfloat16(x);
    __nv_bfloat16 lo = __float2bfloat16(x - __bfloat162float(hi));
    unsigned short* p = g_XB + (size_t)r * K3;
    p[k]            = __bfloat16_as_ushort(hi);
    p[KB16 + k]     = __bfloat16_as_ushort(lo);
    p[2 * KB16 + k] = __bfloat16_as_ushort(hi);
}

// ---------------- warp-level bf16 MMA ----------------
__device__ __forceinline__ void mma16816(float* d,
                                         const unsigned* a,
                                         const unsigned* b) {
    asm volatile(
        "mma.sync.aligned.m16n8k16.row.col.f32.bf16.bf16.f32 "
        "{%0,%1,%2,%3}, {%4,%5,%6,%7}, {%8,%9}, {%0,%1,%2,%3};"
        : "+f"(d[0]), "+f"(d[1]), "+f"(d[2]), "+f"(d[3])
        : "r"(a[0]), "r"(a[1]), "r"(a[2]), "r"(a[3]),
          "r"(b[0]), "r"(b[1]));
}

// ---------------------------------------------------------------------------
// Tensor-core input GEMM (R15: 128x128x32, warp 64x32, dead-tile skip).
// ---------------------------------------------------------------------------
#define KPITCH 40
#define NCHUNK 30

__global__ void __launch_bounds__(256) tc_embed_gemm(
    const float* __restrict__ b_ih,
    const float* __restrict__ b_hh,
    const int*   __restrict__ lengths)
{
    __shared__ __align__(16) unsigned short As[2][128 * KPITCH];
    __shared__ __align__(16) unsigned short Bs[2][128 * KPITCH];
    __shared__ float sbias[128];

    const int mt = blockIdx.y;
    const int nt = blockIdx.x;

    // dead-tile skip (uniform across block)
    if (lengths[mt >> 2] <= (mt & 3) * 128) return;

    const int tid = threadIdx.x;
    const int wid = tid >> 5;
    const int lane = tid & 31;
    const int g   = lane >> 2;
    const int t2  = lane & 3;
    const int wm  = wid >> 2;
    const int wn  = wid & 3;

    if (tid < 128) {
        int n = nt * 128 + tid;
        sbias[tid] = b_ih[n] + b_hh[n];
    }

    const unsigned short* Abase = g_XB + (size_t)(mt * 128) * K3;
    const unsigned short* Bbase = g_WB + (size_t)(nt * 128) * K3;

    unsigned a_sm = 0, b_sm = 0;
    asm("{ .reg .u64 t; cvta.to.shared.u64 t, %1; cvt.u32.u64 %0, t; }"
        : "=r"(a_sm) : "l"((const void*)As));
    asm("{ .reg .u64 t; cvta.to.shared.u64 t, %1; cvt.u32.u64 %0, t; }"
        : "=r"(b_sm) : "l"((const void*)Bs));

#define LOAD_CHUNK(buf, c) do {                                               \
    _Pragma("unroll")                                                         \
    for (int i = 0; i < 2; i++) {                                             \
        int lin = tid + i * 256;                                              \
        int row = lin >> 2;                                                   \
        int q   = lin & 3;                                                    \
        cp16(a_sm + (buf) * (128 * KPITCH * 2) + row * (KPITCH * 2) + q * 16, \
             Abase + (size_t)row * K3 + (c) * 32 + q * 8);                    \
    }                                                                         \
    _Pragma("unroll")                                                         \
    for (int i = 0; i < 2; i++) {                                             \
        int lin = tid + i * 256;                                              \
        int row = lin >> 2;                                                   \
        int q   = lin & 3;                                                    \
        cp16(b_sm + (buf) * (128 * KPITCH * 2) + row * (KPITCH * 2) + q * 16, \
             Bbase + (size_t)row * K3 + (c) * 32 + q * 8);                    \
    }                                                                         \
    CP_COMMIT();                                                              \
} while (0)

    float acc[4][4][4];
#pragma unroll
    for (int mf = 0; mf < 4; mf++)
#pragma unroll
        for (int nf = 0; nf < 4; nf++)
#pragma unroll
            for (int q = 0; q < 4; q++) acc[mf][nf][q] = 0.f;

    LOAD_CHUNK(0, 0);

#pragma unroll 1
    for (int c = 0; c < NCHUNK; c++) {
        const int buf = c & 1;
        if (c + 1 < NCHUNK) {
            LOAD_CHUNK(buf ^ 1, c + 1);
            CP_WAIT(1);
        } else {
            CP_WAIT(0);
        }
        __syncthreads();

        const unsigned short* Ab = As[buf];
        const unsigned short* Bb = Bs[buf];

#pragma unroll
        for (int k16 = 0; k16 < 2; k16++) {
            const int ko = k16 * 16 + t2 * 2;
            unsigned af[4][4];
#pragma unroll
            for (int mf = 0; mf < 4; mf++) {
                int row = wm * 64 + mf * 16 + g;
                af[mf][0] = *(const unsigned*)&Ab[row * KPITCH + ko];
                af[mf][1] = *(const unsigned*)&Ab[(row + 8) * KPITCH + ko];
                af[mf][2] = *(const unsigned*)&Ab[row * KPITCH + ko + 8];
                af[mf][3] = *(const unsigned*)&Ab[(row + 8) * KPITCH + ko + 8];
            }
            unsigned bfr[4][2];
#pragma unroll
            for (int nf = 0; nf < 4; nf++) {
                int col = wn * 32 + nf * 8 + g;
                bfr[nf][0] = *(const unsigned*)&Bb[col * KPITCH + ko];
                bfr[nf][1] = *(const unsigned*)&Bb[col * KPITCH + ko + 8];
            }
#pragma unroll
            for (int mf = 0; mf < 4; mf++)
#pragma unroll
                for (int nf = 0; nf < 4; nf++)
                    mma16816(acc[mf][nf], af[mf], bfr[nf]);
        }
        __syncthreads();
    }
#undef LOAD_CHUNK

    const int r0 = mt * 128 + wm * 64;
#pragma unroll
    for (int mf = 0; mf < 4; mf++) {
#pragma unroll
        for (int nf = 0; nf < 4; nf++) {
            int nl = wn * 32 + nf * 8 + t2 * 2;
            int n  = nt * 128 + nl;
            float bx = sbias[nl];
            float by = sbias[nl + 1];
            int ra = r0 + mf * 16 + g;
            int rb = ra + 8;
            *(float2*)(g_XG + (size_t)ra * G4 + n) =
                make_float2(acc[mf][nf][0] + bx, acc[mf][nf][1] + by);
            *(float2*)(g_XG + (size_t)rb * G4 + n) =
                make_float2(acc[mf][nf][2] + bx, acc[mf][nf][3] + by);
        }
    }
}

// ---------------------------------------------------------------------------
// Persistent LSTM — EXACT R15 structure and GEMV (measured best).
// ---------------------------------------------------------------------------
__global__ void __launch_bounds__(256, 1) lstm_persistent(
    const float* __restrict__ W_hh,
    const int*   __restrict__ lengths,
    float* __restrict__ out)
{
    __shared__ float sm_h[16 * HC];
    __shared__ float Ex[64 * 17];
    __shared__ int   sl[16];

    const int tid  = threadIdx.x;
    const int bk   = blockIdx.x;
    const int jg   = bk >> 2;
    const int bq   = bk & 3;
    const int lane = tid & 31;
    const int w    = tid >> 5;
    const int rp   = lane >> 3;
    const int kc   = lane & 7;

    const int lr0 = w * 8 + rp * 2;
    const int lr1 = lr0 + 1;
    const int row0 = ((lr0 >> 4) << 9) + jg * 16 + (lr0 & 15);
    const int row1 = ((lr1 >> 4) << 9) + jg * 16 + (lr1 & 15);

    ull W0[32], W1[32];
#pragma unroll
    for (int m = 0; m < 16; m++) {
        const float* p0 = W_hh + (size_t)row0 * HC + m * 32 + kc * 4;
        const float* p1 = W_hh + (size_t)row1 * HC + m * 32 + kc * 4;
        ulonglong2 v0 = *(const ulonglong2*)p0;
        ulonglong2 v1 = *(const ulonglong2*)p1;
        W0[2 * m] = v0.x; W0[2 * m + 1] = v0.y;
        W1[2 * m] = v1.x; W1[2 * m + 1] = v1.y;
    }

    const unsigned sm_h_u32 = (unsigned)__cvta_generic_to_shared(sm_h);

    // replay-safe epoch base (read by all threads before any arrive)
    const unsigned e0 = ld_acq(&g_epoch4[bq]);

    if (tid < 16) sl[tid] = lengths[bq * 16 + tid];

    const int jl   = tid & 15;
    const int bl   = tid >> 4;
    const int b_pt = bq * 16 + bl;
    const int j_pt = jg * 16 + jl;
    float h_st = 0.f, c_st = 0.f;

    stcg_f(&g_H[0][(b_pt << 9) + j_pt], 0.f);

    __syncthreads();
    int gmax = sl[0];
#pragma unroll
    for (int i = 1; i < 16; i++) gmax = max(gmax, sl[i]);
    const int len_b = sl[bl];

    if (tid == 0) bar_arrive(bq, e0 + 1);
    bar_wait(bq, e0 + 1);

    // batch-major xg rows: base row = b_pt*512
    const float* xg_base = g_XG + ((size_t)b_pt << 9) * G4;

    float xi, xf, xgv, xo;
    {
        const float* xg = xg_base;      // t = 0
        xi  = ldcg_f(xg + j_pt);
        xf  = ldcg_f(xg + 512 + j_pt);
        xgv = ldcg_f(xg + 1024 + j_pt);
        xo  = ldcg_f(xg + 1536 + j_pt);
    }

#define GEMV_BATCH(bb)                                                        \
    if (t < sl[bb]) {                                                         \
        const float* hb = sm_h + ((bb) << 9) + (kc << 2);                     \
        ull a0 = 0ull, a1 = 0ull;                                             \
        _Pragma("unroll")                                                     \
        for (int m = 0; m < 16; m++) {                                        \
            ulonglong2 hv = *(const ulonglong2*)(hb + (m << 5));              \
            a0 = ffma2(W0[2 * m],     hv.x, a0);                              \
            a0 = ffma2(W0[2 * m + 1], hv.y, a0);                              \
            a1 = ffma2(W1[2 * m],     hv.x, a1);                              \
            a1 = ffma2(W1[2 * m + 1], hv.y, a1);                              \
        }                                                                     \
        float s0 = hsum2(a0);                                                 \
        float s1 = hsum2(a1);                                                 \
        s0 += __shfl_xor_sync(0xffffffffu, s0, 1);                            \
        s0 += __shfl_xor_sync(0xffffffffu, s0, 2);                            \
        s0 += __shfl_xor_sync(0xffffffffu, s0, 4);                            \
        s1 += __shfl_xor_sync(0xffffffffu, s1, 1);                            \
        s1 += __shfl_xor_sync(0xffffffffu, s1, 2);                            \
        s1 += __shfl_xor_sync(0xffffffffu, s1, 4);                            \
        if (kc == 0) {                                                        \
            Ex[lr0 * 17 + (bb)] = s0;                                         \
            Ex[lr1 * 17 + (bb)] = s1;                                         \
        }                                                                     \
    }

#pragma unroll 1
    for (int t = 0; t < gmax; t++) {
        const int p = t & 1;
        const float* h_in = g_H[p] + ((bq * 16) << 9);

        // ---- stage this bq's h (16 rows x 512) in two 8-batch halves ----
#pragma unroll
        for (int grp = 0; grp < 2; grp++) {
#pragma unroll
            for (int i = 0; i < 4; i++) {
                int lin = tid + (i << 8);
                int r   = lin >> 7;
                int off = (lin & 127) << 2;
                int b   = grp * 8 + r;
                cp16(sm_h_u32 + (unsigned)((((b << 9) + off) << 2)),
                     h_in + (b << 9) + off);
            }
            CP_COMMIT();
        }
        CP_WAIT(1);
        __syncthreads();

#pragma unroll 2
        for (int bb = 0; bb < 8; bb++) GEMV_BATCH(bb)

        CP_WAIT(0);
        __syncthreads();

#pragma unroll 2
        for (int bb = 8; bb < 16; bb++) GEMV_BATCH(bb)

        __syncthreads();

        const bool msk = (t < len_b);
        if (msk) {
            float pi = xi  + Ex[(0  + jl) * 17 + bl];
            float pf = xf  + Ex[(16 + jl) * 17 + bl];
            float pg = xgv + Ex[(32 + jl) * 17 + bl];
            float po = xo  + Ex[(48 + jl) * 17 + bl];

            float gi = fsigmoid(pi);
            float gf = fsigmoid(pf);
            float gg = ftanh(pg);
            float go = fsigmoid(po);

            c_st = gf * c_st + gi * gg;
            h_st = go * ftanh(c_st);
        }
        stcg_f(&g_H[p ^ 1][(b_pt << 9) + j_pt], h_st);

        const bool last = (t + 1 >= gmax);
        __syncthreads();                 // all publishes issued
        if (!last && tid == 0) bar_arrive(bq, e0 + t + 2);

        // DRAM out-stores + next-step xg prefetch hide in the barrier shadow
        if (msk) {
            size_t o = (size_t)b_pt * (SEQT * HC) + (size_t)t * HC + j_pt;
            out[o]                = h_st;
            out[OUT_CELL_OFF + o] = c_st;
        }
        if (t + 1 < len_b) {
            const float* xg = xg_base + (size_t)(t + 1) * G4;
            xi  = ldcg_f(xg + j_pt);
            xf  = ldcg_f(xg + 512 + j_pt);
            xgv = ldcg_f(xg + 1024 + j_pt);
            xo  = ldcg_f(xg + 1536 + j_pt);
        }

        if (!last) bar_wait(bq, e0 + t + 2);
    }

    {
        size_t e = (size_t)b_pt * HC + j_pt;
        out[OUT_H_OFF + e] = h_st;
        out[OUT_C_OFF + e] = c_st;
    }
#undef GEMV_BATCH
}

// ---------------------------------------------------------------------------
extern "C" void kernel_launch(void* const* d_in, const int* in_sizes, int n_in,
                              void* d_out, int out_size) {
    const int*   seq     = (const int*)d_in[0];
    const int*   lengths = (const int*)d_in[1];
    const float* emb     = (const float*)d_in[2];
    const float* W_ih    = (const float*)d_in[3];
    const float* W_hh    = (const float*)d_in[4];
    const float* b_ih    = (const float*)d_in[5];
    const float* b_hh    = (const float*)d_in[6];
    float* out = (float*)d_out;

    // zero only dead cells of output + cell regions (2 regions via grid.y)
    zero_out<<<dim3((unsigned)(OUT_CELL_OFF / (256 * 4)), 2), 256>>>(out, lengths);
    prep_WB<<<(G4 * KB16) / 256, 256>>>(W_ih);
    prep_X<<<(unsigned)(((size_t)SEQT * BATCH * KB16) / 256), 256>>>(seq, emb, lengths);
    tc_embed_gemm<<<dim3(G4 / 128, (SEQT * BATCH) / 128), 256>>>(b_ih, b_hh, lengths);
    lstm_persistent<<<NBLK, 256>>>(W_hh, lengths, out);
}